// round 2
// baseline (speedup 1.0000x reference)
#include <cuda_runtime.h>

// CosinLoss fused: loss = mean_i( 1 - dot(pc_i,aug_i) / (max(||pc_i||,eps)*max(||aug_i||,eps)) )
// N=16384 rows, D=1024 fp32. HBM-streaming (128 MiB read).
// One warp per row, 8 rows per CTA, 2048 CTAs. Last-CTA-done final reduce.

#define CL_N   16384
#define CL_D   1024
#define CL_EPS 1e-12f
#define GRID   2048   // = CL_N / 8 warps per CTA
#define TPB    256

__device__ float        g_part[GRID];
__device__ unsigned int g_count = 0;

__global__ __launch_bounds__(TPB, 4)
void cos_loss_fused(const float* __restrict__ pc, const float* __restrict__ aug,
                    float* __restrict__ out) {
    const int warp = threadIdx.x >> 5;
    const int lane = threadIdx.x & 31;
    const int row  = blockIdx.x * 8 + warp;   // one warp per row, exact cover

    const float4* __restrict__ p4 = reinterpret_cast<const float4*>(pc  + (size_t)row * CL_D);
    const float4* __restrict__ a4 = reinterpret_cast<const float4*>(aug + (size_t)row * CL_D);

    // Front-batch 16 LDG.128 per thread for deep MLP.
    float4 p[8], a[8];
    #pragma unroll
    for (int i = 0; i < 8; i++) p[i] = p4[lane + 32 * i];
    #pragma unroll
    for (int i = 0; i < 8; i++) a[i] = a4[lane + 32 * i];

    float dot = 0.0f, npp = 0.0f, naa = 0.0f;
    #pragma unroll
    for (int i = 0; i < 8; i++) {
        dot += p[i].x * a[i].x + p[i].y * a[i].y + p[i].z * a[i].z + p[i].w * a[i].w;
        npp += p[i].x * p[i].x + p[i].y * p[i].y + p[i].z * p[i].z + p[i].w * p[i].w;
        naa += a[i].x * a[i].x + a[i].y * a[i].y + a[i].z * a[i].z + a[i].w * a[i].w;
    }

    // Warp reduce (3 values)
    #pragma unroll
    for (int off = 16; off > 0; off >>= 1) {
        dot += __shfl_down_sync(0xFFFFFFFFu, dot, off);
        npp += __shfl_down_sync(0xFFFFFFFFu, npp, off);
        naa += __shfl_down_sync(0xFFFFFFFFu, naa, off);
    }

    __shared__ float s_loss[8];
    __shared__ int   s_last;
    if (lane == 0) {
        float np_ = fmaxf(sqrtf(npp), CL_EPS);
        float na_ = fmaxf(sqrtf(naa), CL_EPS);
        s_loss[warp] = 1.0f - dot / (np_ * na_);
    }
    __syncthreads();

    // Thread 0: CTA partial -> global, then check if we're the last CTA.
    if (threadIdx.x == 0) {
        float part = 0.0f;
        #pragma unroll
        for (int i = 0; i < 8; i++) part += s_loss[i];
        g_part[blockIdx.x] = part;
        __threadfence();
        unsigned int prev = atomicInc(&g_count, GRID - 1); // wraps to 0 at GRID-1
        s_last = (prev == GRID - 1);
    }
    __syncthreads();

    if (s_last) {
        // Last CTA: reduce all 2048 partials (fixed order -> deterministic).
        const int t = threadIdx.x;
        float s = 0.0f;
        #pragma unroll
        for (int i = 0; i < GRID / TPB; i++)   // 8 partials per thread
            s += g_part[t + i * TPB];

        #pragma unroll
        for (int off = 16; off > 0; off >>= 1)
            s += __shfl_down_sync(0xFFFFFFFFu, s, off);

        __shared__ float s_sum[8];
        if (lane == 0) s_sum[warp] = s;
        __syncthreads();

        if (warp == 0) {
            s = (lane < 8) ? s_sum[lane] : 0.0f;
            #pragma unroll
            for (int off = 4; off > 0; off >>= 1)
                s += __shfl_down_sync(0xFFFFFFFFu, s, off);
            if (lane == 0)
                out[0] = s * (1.0f / (float)CL_N);
        }
    }
}

extern "C" void kernel_launch(void* const* d_in, const int* in_sizes, int n_in,
                              void* d_out, int out_size) {
    const float* pc  = (const float*)d_in[0];
    const float* aug = (const float*)d_in[1];
    float* out = (float*)d_out;

    cos_loss_fused<<<GRID, TPB>>>(pc, aug, out);
}